// round 11
// baseline (speedup 1.0000x reference)
#include <cuda_runtime.h>
#include <cstdint>

// UAVid palette -> class id, packed key (r<<16)|(g<<8)|b:
// 0: 0x000000  1: 0x800000  2: 0x804080  3: 0xC000C0
// 4: 0x008000  5: 0x808000  6: 0x404000  7: 0x400080
// Unmatched keys (incl. 0) -> class 0.
//
// Converged config (R3==R10 best): 4 px/thread, 3 coalesced int4 loads +
// 1 float4 store, 256 threads, exact grid. 18.9us kernel = ~99% of the
// 133MB / 5.85TB/s memory floor on this part. All other axes (MLP, cache
// hints, persistency, block size, unrolling) measured neutral or worse.

__device__ __forceinline__ float classify(int r, int g, int b) {
    unsigned key = ((unsigned)r << 16) | ((unsigned)g << 8) | (unsigned)b;
    int c = 0;
    c += (key == 0x800000u) ? 1 : 0;
    c += (key == 0x804080u) ? 2 : 0;
    c += (key == 0xC000C0u) ? 3 : 0;
    c += (key == 0x008000u) ? 4 : 0;
    c += (key == 0x808000u) ? 5 : 0;
    c += (key == 0x404000u) ? 6 : 0;
    c += (key == 0x400080u) ? 7 : 0;
    return (float)c;
}

__global__ void __launch_bounds__(256)
uavid_vec4_f32_kernel(const int4* __restrict__ rp,
                      const int4* __restrict__ gp,
                      const int4* __restrict__ bp,
                      float4* __restrict__ out,
                      int n4) {
    int i = blockIdx.x * blockDim.x + threadIdx.x;
    if (i >= n4) return;
    int4 r = rp[i];
    int4 g = gp[i];
    int4 b = bp[i];
    float4 o;
    o.x = classify(r.x, g.x, b.x);
    o.y = classify(r.y, g.y, b.y);
    o.z = classify(r.z, g.z, b.z);
    o.w = classify(r.w, g.w, b.w);
    out[i] = o;
}

__global__ void uavid_tail_f32_kernel(const int* __restrict__ rp,
                                      const int* __restrict__ gp,
                                      const int* __restrict__ bp,
                                      float* __restrict__ out,
                                      int start, int hw) {
    int i = start + blockIdx.x * blockDim.x + threadIdx.x;
    if (i >= hw) return;
    out[i] = classify(rp[i], gp[i], bp[i]);
}

extern "C" void kernel_launch(void* const* d_in, const int* in_sizes, int n_in,
                              void* d_out, int out_size) {
    const int* t = (const int*)d_in[0];
    int n  = in_sizes[0];     // 3 * H * W
    int hw = n / 3;           // H * W
    const int* rp = t;
    const int* gp = t + hw;
    const int* bp = t + 2 * hw;

    int n4  = hw >> 2;        // pixel-quads
    int rem = hw & 3;

    if (n4 > 0) {
        int threads = 256;
        int blocks  = (n4 + threads - 1) / threads;
        uavid_vec4_f32_kernel<<<blocks, threads>>>(
            (const int4*)rp, (const int4*)gp, (const int4*)bp,
            (float4*)d_out, n4);
    }
    if (rem > 0) {
        uavid_tail_f32_kernel<<<1, 256>>>(rp, gp, bp,
                                          (float*)d_out, n4 << 2, hw);
    }
}

// round 12
// speedup vs baseline: 1.0557x; 1.0557x over previous
#include <cuda_runtime.h>
#include <cstdint>

// UAVid palette -> class id, packed key (r<<16)|(g<<8)|b:
// 0: 0x000000  1: 0x800000  2: 0x804080  3: 0xC000C0
// 4: 0x008000  5: 0x808000  6: 0x404000  7: 0x400080
// Unmatched keys (incl. 0) -> class 0.
//
// Converged config: 4 px/thread, 3 coalesced int4 loads + 1 float4 store,
// 256 threads, exact grid. Best kernel 18.88us = ~99% of the 133MB/5.85TB/s
// memory floor. Identical-source reruns span 18.9-19.6us (DVFS noise);
// all alternative configs (MLP, cache hints, persistency, block size,
// unrolling) measured within-noise or worse across R3-R11.

__device__ __forceinline__ float classify(int r, int g, int b) {
    unsigned key = ((unsigned)r << 16) | ((unsigned)g << 8) | (unsigned)b;
    int c = 0;
    c += (key == 0x800000u) ? 1 : 0;
    c += (key == 0x804080u) ? 2 : 0;
    c += (key == 0xC000C0u) ? 3 : 0;
    c += (key == 0x008000u) ? 4 : 0;
    c += (key == 0x808000u) ? 5 : 0;
    c += (key == 0x404000u) ? 6 : 0;
    c += (key == 0x400080u) ? 7 : 0;
    return (float)c;
}

__global__ void __launch_bounds__(256)
uavid_vec4_f32_kernel(const int4* __restrict__ rp,
                      const int4* __restrict__ gp,
                      const int4* __restrict__ bp,
                      float4* __restrict__ out,
                      int n4) {
    int i = blockIdx.x * blockDim.x + threadIdx.x;
    if (i >= n4) return;
    int4 r = rp[i];
    int4 g = gp[i];
    int4 b = bp[i];
    float4 o;
    o.x = classify(r.x, g.x, b.x);
    o.y = classify(r.y, g.y, b.y);
    o.z = classify(r.z, g.z, b.z);
    o.w = classify(r.w, g.w, b.w);
    out[i] = o;
}

__global__ void uavid_tail_f32_kernel(const int* __restrict__ rp,
                                      const int* __restrict__ gp,
                                      const int* __restrict__ bp,
                                      float* __restrict__ out,
                                      int start, int hw) {
    int i = start + blockIdx.x * blockDim.x + threadIdx.x;
    if (i >= hw) return;
    out[i] = classify(rp[i], gp[i], bp[i]);
}

extern "C" void kernel_launch(void* const* d_in, const int* in_sizes, int n_in,
                              void* d_out, int out_size) {
    const int* t = (const int*)d_in[0];
    int n  = in_sizes[0];     // 3 * H * W
    int hw = n / 3;           // H * W
    const int* rp = t;
    const int* gp = t + hw;
    const int* bp = t + 2 * hw;

    int n4  = hw >> 2;        // pixel-quads
    int rem = hw & 3;

    if (n4 > 0) {
        int threads = 256;
        int blocks  = (n4 + threads - 1) / threads;
        uavid_vec4_f32_kernel<<<blocks, threads>>>(
            (const int4*)rp, (const int4*)gp, (const int4*)bp,
            (float4*)d_out, n4);
    }
    if (rem > 0) {
        uavid_tail_f32_kernel<<<1, 256>>>(rp, gp, bp,
                                          (float*)d_out, n4 << 2, hw);
    }
}